// round 14
// baseline (speedup 1.0000x reference)
#include <cuda_runtime.h>
#include <cuda_bf16.h>
#include <math.h>
#include <stdint.h>

#define T_LEN 512
#define BATCH 32
#define EMB   41
#define HID   800
#define G4    3200
#define IN0   42
#define IN1   1600
#define UNITS 20
#define MTOT  (T_LEN*BATCH)   // 16384
#define NTOT  6400
#define KTOT  1600

// ---------------- device scratch ----------------
__device__ float g_xw[2u * T_LEN * BATCH * G4];
__device__ float g_ang[MTOT * 3];
__device__ __nv_bfloat16 g_h0h[(size_t)MTOT * IN1];
__device__ __nv_bfloat16 g_h0l[(size_t)MTOT * IN1];
__device__ __nv_bfloat16 g_h1h[(size_t)MTOT * IN1];
__device__ __nv_bfloat16 g_h1l[(size_t)MTOT * IN1];
__device__ __nv_bfloat16 g_wh[(size_t)NTOT * KTOT];
__device__ __nv_bfloat16 g_wl[(size_t)NTOT * KTOT];
__device__ __nv_bfloat16 g_whhh0[(size_t)2 * G4 * HID];
__device__ __nv_bfloat16 g_whhl0[(size_t)2 * G4 * HID];
__device__ __nv_bfloat16 g_whhh1[(size_t)2 * G4 * HID];
__device__ __nv_bfloat16 g_whhl1[(size_t)2 * G4 * HID];
__device__ unsigned g_barcnt[4];   // [dir*2 + half]
__device__ unsigned g_bargen[4];

__device__ __forceinline__ float sigf(float x) { return 1.0f / (1.0f + __expf(-x)); }
__device__ __forceinline__ float tanhfast(float x) {
    float a = fabsf(x);
    float e = __expf(2.0f * a);
    float r = 1.0f - 2.0f / (e + 1.0f);
    return copysignf(r, x);
}
__device__ __forceinline__ uint32_t s2u(const void* p) {
    uint32_t a; asm("{.reg .u64 t; cvta.to.shared.u64 t, %1; cvt.u32.u64 %0, t;}" : "=r"(a) : "l"(p));
    return a;
}
__device__ __forceinline__ void ldsm4(uint32_t& r0, uint32_t& r1, uint32_t& r2,
                                      uint32_t& r3, uint32_t addr) {
    asm volatile("ldmatrix.sync.aligned.m8n8.x4.shared.b16 {%0,%1,%2,%3}, [%4];"
                 : "=r"(r0), "=r"(r1), "=r"(r2), "=r"(r3) : "r"(addr));
}
__device__ __forceinline__ void ldsm2(uint32_t& r0, uint32_t& r1, uint32_t addr) {
    asm volatile("ldmatrix.sync.aligned.m8n8.x2.shared.b16 {%0,%1}, [%2];"
                 : "=r"(r0), "=r"(r1) : "r"(addr));
}
__device__ __forceinline__ void mma_bf16(float* c, const uint32_t* a, const uint32_t* b) {
    asm volatile("mma.sync.aligned.m16n8k16.row.col.f32.bf16.bf16.f32 "
                 "{%0,%1,%2,%3}, {%4,%5,%6,%7}, {%8,%9}, {%0,%1,%2,%3};"
                 : "+f"(c[0]), "+f"(c[1]), "+f"(c[2]), "+f"(c[3])
                 : "r"(a[0]), "r"(a[1]), "r"(a[2]), "r"(a[3]), "r"(b[0]), "r"(b[1]));
}
__device__ __forceinline__ unsigned atom_add_acqrel(unsigned* p) {
    unsigned old;
    asm volatile("atom.add.acq_rel.gpu.u32 %0, [%1], 1;" : "=r"(old) : "l"(p) : "memory");
    return old;
}
__device__ __forceinline__ unsigned ld_acq(unsigned* p) {
    unsigned v;
    asm volatile("ld.acquire.gpu.u32 %0, [%1];" : "=r"(v) : "l"(p) : "memory");
    return v;
}
__device__ __forceinline__ void st_rel(unsigned* p, unsigned v) {
    asm volatile("st.release.gpu.u32 [%0], %1;" :: "l"(p), "r"(v) : "memory");
}

// ---------------- layer0 input projection ----------------
__global__ void k_xw0(const float* __restrict__ seq, const float* __restrict__ w_ih,
                      const float* __restrict__ bias) {
    __shared__ float xs[BATCH * IN0];
    int t = blockIdx.y, d = blockIdx.z;
    int g = blockIdx.x * 128 + threadIdx.x;
    for (int e = threadIdx.x; e < BATCH * IN0; e += 128) {
        int b = e / IN0, i = e % IN0;
        xs[e] = (i < EMB) ? seq[(size_t)(t * BATCH + b) * EMB + i] : (float)t;
    }
    __syncthreads();
    float acc[BATCH];
    float bv = bias[d * G4 + g];
#pragma unroll
    for (int b = 0; b < BATCH; b++) acc[b] = bv;
    const float* wrow = w_ih + (size_t)(d * G4 + g) * IN0;
#pragma unroll
    for (int i = 0; i < IN0; i++) {
        float wv = wrow[i];
#pragma unroll
        for (int b = 0; b < BATCH; b++) acc[b] += wv * xs[b * IN0 + i];
    }
    size_t base = ((size_t)(d * T_LEN + t) * BATCH) * G4 + g;
#pragma unroll
    for (int b = 0; b < BATCH; b++) g_xw[base + (size_t)b * G4] = acc[b];
}

// ---------------- combined bf16 split converter (+ barrier init) --------
#define N_WHH (2 * G4 * HID)          // 5,120,000
#define N_WIH1 (NTOT * KTOT)          // 10,240,000
__global__ void k_cvt_all(const float* __restrict__ whh0,
                          const float* __restrict__ whh1,
                          const float* __restrict__ wih1) {
    if (blockIdx.x == 0 && threadIdx.x < 4) {
        g_barcnt[threadIdx.x] = 0; g_bargen[threadIdx.x] = 0;
    }
    size_t i = (size_t)blockIdx.x * 256 + threadIdx.x;
    const float* src;
    __nv_bfloat16 *dh, *dl;
    size_t k;
    if (i < (size_t)N_WHH) {
        src = whh0; dh = g_whhh0; dl = g_whhl0; k = i;
    } else if (i < (size_t)2 * N_WHH) {
        src = whh1; dh = g_whhh1; dl = g_whhl1; k = i - N_WHH;
    } else if (i < (size_t)2 * N_WHH + N_WIH1) {
        src = wih1; dh = g_wh; dl = g_wl; k = i - 2 * (size_t)N_WHH;
    } else return;
    float v = src[k];
    __nv_bfloat16 h = __float2bfloat16(v);
    dh[k] = h;
    dl[k] = __float2bfloat16(v - __bfloat162float(h));
}

// filler so the lstm lands at ncu's captured slot (#4)
__global__ void k_nop() {}

// ---------------- persistent LSTM: interleaved batch-half chains --------
// grid (50, 2), 256 thr (8 warps = 2 K-slices x 4 N-groups, warp m16n16k400
// per half). W_hi in registers, W_lo smem. Two independent 16-row chains
// per direction with separate barriers; arrive after one half's epilogue,
// wait at the next step -> barrier/L2 latency hidden behind the other half.
#define WL_OFF 0
#define R1_OFF 103424
#define AHALF  51712
#define LSTM_SMEM 206848

__global__ void __launch_bounds__(256, 1)
k_lstm_mma(int layer) {
    extern __shared__ __align__(16) uint8_t sm[];
    const uint32_t sbase = s2u(sm);
    const int tid = threadIdx.x, lane = tid & 31, w = tid >> 5;
    const int wk = w >> 2;          // 0..1 : K slice (k400)
    const int ng = w & 3;           // 0..3 : N group (n16)
    const int d = blockIdx.y, j0 = blockIdx.x * 16;
    const int nblk = gridDim.x;

    __nv_bfloat16* hh = layer ? g_h1h : g_h0h;
    __nv_bfloat16* hl = layer ? g_h1l : g_h0l;
    const __nv_bfloat16* whhh = layer ? g_whhh1 : g_whhh0;
    const __nv_bfloat16* whhl = layer ? g_whhl1 : g_whhl0;

    // stage W_lo -> WL region, W_hi -> R1 region (temporarily)
    for (int idx = tid; idx < 12800; idx += 256) {
        int s = idx >= 6400;
        int e = idx - s * 6400;
        int r = e / 100, c = e % 100;
        int grow = (r >> 4) * HID + j0 + (r & 15);
        const __nv_bfloat16* src = (s ? whhh : whhl)
                                 + ((size_t)(d * G4 + grow) * HID + c * 8);
        *(uint4*)(sm + (s ? R1_OFF : WL_OFF) + r * 1616 + c * 16) = *(const uint4*)src;
    }
    __syncthreads();

    const int lr = lane & 7, q = lane >> 3;

    // preload W_hi fragments into registers: bh[sub][t16*2 + {0,1}]
    uint32_t bh[2][50];
#pragma unroll
    for (int sub = 0; sub < 2; sub++) {
        uint32_t b0 = sbase + R1_OFF
                    + (uint32_t)((ng * 16 + sub * 8 + lr) * 1616 + wk * 800 + q * 16);
#pragma unroll
        for (int g = 0; g < 12; g++)
            ldsm4(bh[sub][4 * g], bh[sub][4 * g + 1],
                  bh[sub][4 * g + 2], bh[sub][4 * g + 3], b0 + g * 64);
        uint32_t bx = sbase + R1_OFF
                    + (uint32_t)((ng * 16 + sub * 8 + lr) * 1616 + wk * 800 + 768
                                 + ((lane >> 3) & 1) * 16);
        ldsm2(bh[sub][48], bh[sub][49], bx);
    }
    __syncthreads();   // R1 region now free for per-half A buffers

    const int a_row_q = (q & 1) * 8 + lr;     // 0..15 within half
    const int a_colq  = (q >> 1) * 16;
    uint32_t blb[2];
#pragma unroll
    for (int sub = 0; sub < 2; sub++)
        blb[sub] = sbase + WL_OFF
                 + (uint32_t)((ng * 16 + sub * 8 + lr) * 1616 + wk * 800
                              + ((lane >> 3) & 1) * 16);

    // A staging: 8 thr per (sp,row-in-half); 13 strided chunks each
    const int cq = tid & 7, combo = tid >> 3;          // combo 0..31
    const int ssp = combo >> 4, srow = combo & 15;
    const __nv_bfloat16* hsrc_base = ssp ? hl : hh;

    // epilogue: 1 (row-in-half, jj) pair per thread
    const int ebr = tid >> 4, ejj = tid & 15;
    float creg[2] = {0.0f, 0.0f};

    for (int t = 0; t < T_LEN; t++) {
        const int tt = d ? (T_LEN - 1 - t) : t;
        const int tp = d ? tt + 1 : t - 1;
        const size_t xwb = ((size_t)(d * T_LEN + tt) * BATCH) * G4;

#pragma unroll 1
        for (int half = 0; half < 2; half++) {
            const int bidx = d * 2 + half;
            const int eb = half * 16 + ebr;

            // xg prefetch (independent of barrier)
            float xg[4];
#pragma unroll
            for (int e = 0; e < 4; e++)
                xg[e] = __ldg(g_xw + xwb + (size_t)eb * G4 + e * HID + j0 + ejj);

            float acc[2][4];
#pragma unroll
            for (int sub = 0; sub < 2; sub++)
#pragma unroll
                for (int i = 0; i < 4; i++) acc[sub][i] = 0.0f;

            if (t > 0) {
                // wait for this half-chain's step t-1 writes
                if (tid == 0) {
                    while ((int)ld_acq(&g_bargen[bidx]) < t) { }
                }
                __syncthreads();

                // stage A half (hi+lo, 51.7KB)
                const __nv_bfloat16* hsrc = hsrc_base
                    + (size_t)(tp * BATCH + half * 16 + srow) * IN1 + d * HID + cq * 8;
                const uint32_t adst = (uint32_t)(R1_OFF + half * AHALF
                                     + ssp * 25856 + srow * 1616 + cq * 16);
#pragma unroll
                for (int j = 0; j < 13; j++) {
                    if (cq + 8 * j < 100)
                        *(uint4*)(sm + adst + j * 128) = *(const uint4*)(hsrc + j * 64);
                }
                __syncthreads();

#pragma unroll
                for (int t16 = 0; t16 < 25; t16++) {
                    uint32_t ah[4], al[4], bl0[2], bl1[2];
                    uint32_t aa = sbase + (uint32_t)(R1_OFF + half * AHALF
                                + a_row_q * 1616 + wk * 800 + t16 * 32 + a_colq);
                    ldsm4(ah[0], ah[1], ah[2], ah[3], aa);
                    ldsm4(al[0], al[1], al[2], al[3], aa + 25856);
                    ldsm2(bl0[0], bl0[1], blb[0] + t16 * 32);
                    ldsm2(bl1[0], bl1[1], blb[1] + t16 * 32);
                    mma_bf16(acc[0], ah, &bh[0][t16 * 2]);
                    mma_bf16(acc[0], ah, bl0);
                    mma_bf16(acc[0], al, &bh[0][t16 * 2]);
                    mma_bf16(acc[1], ah, &bh[1][t16 * 2]);
                    mma_bf16(acc[1], ah, bl1);
                    mma_bf16(acc[1], al, &bh[1][t16 * 2]);
                }
            }

            // stage gates into Gt (aliases this half's A region)
            __syncthreads();
            float* Gt = (float*)(sm + R1_OFF + half * AHALF);   // [32][68]
#pragma unroll
            for (int sub = 0; sub < 2; sub++) {
                int r0 = lane >> 2;
                int c = ng * 16 + sub * 8 + (lane & 3) * 2;
                Gt[(wk * 16 + r0) * 68 + c]           = acc[sub][0];
                Gt[(wk * 16 + r0) * 68 + c + 1]       = acc[sub][1];
                Gt[(wk * 16 + r0 + 8) * 68 + c]       = acc[sub][2];
                Gt[(wk * 16 + r0 + 8) * 68 + c + 1]   = acc[sub][3];
            }
            __syncthreads();

            // epilogue: sum K-slices, add xw, LSTM pointwise (1 pair)
            {
                float g0 = Gt[ebr * 68 + ejj]        + Gt[(16 + ebr) * 68 + ejj]        + xg[0];
                float g1 = Gt[ebr * 68 + 16 + ejj]   + Gt[(16 + ebr) * 68 + 16 + ejj]   + xg[1];
                float g2 = Gt[ebr * 68 + 32 + ejj]   + Gt[(16 + ebr) * 68 + 32 + ejj]   + xg[2];
                float g3 = Gt[ebr * 68 + 48 + ejj]   + Gt[(16 + ebr) * 68 + 48 + ejj]   + xg[3];
                float cold = (t > 0) ? creg[half] : 0.0f;
                float cn = sigf(g1) * cold + sigf(g0) * tanhfast(g2);
                float hn = sigf(g3) * tanhfast(cn);
                creg[half] = cn;
                size_t ho = (size_t)(tt * BATCH + eb) * IN1 + d * HID + j0 + ejj;
                __nv_bfloat16 hhi = __float2bfloat16(hn);
                hh[ho] = hhi;
                hl[ho] = __float2bfloat16(hn - __bfloat162float(hhi));
            }

            // arrive (non-blocking); next step's wait consumes it
            if (t + 1 < T_LEN) {
                __syncthreads();
                if (tid == 0) {
                    unsigned old = atom_add_acqrel(&g_barcnt[bidx]);
                    if (old == (unsigned)(nblk - 1)) {
                        g_barcnt[bidx] = 0;
                        st_rel(&g_bargen[bidx], (unsigned)(t + 1));
                    }
                }
            }
        }
    }
}

// ---------------- xw1: fused single-pass bf16-split GEMM ----------------
#define XW1_SMEM 65536
__global__ void __launch_bounds__(256)
k_xw1_mma(const float* __restrict__ bias) {
    extern __shared__ __align__(1024) uint8_t smx[];
    const uint32_t sbase = s2u(smx);

    const int tid = threadIdx.x;
    const int lane = tid & 31, wid = tid >> 5;
    const int wm = wid >> 2, wn = wid & 3;
    const int lm = lane >> 3, lr = lane & 7;
    const int n0 = blockIdx.x * 128, m0 = blockIdx.y * 128;

    const int a_row_b = wm * 64 + (lm & 1) * 8 + lr;
    const int a_c_b   = (lm >> 1);
    const int b_row_b = wn * 32 + (lm >> 1) * 8 + lr;
    const int b_c_b   = (lm & 1);

    float acc[4][4][4];
#pragma unroll
    for (int i = 0; i < 4; i++)
#pragma unroll
        for (int j = 0; j < 4; j++)
#pragma unroll
            for (int q = 0; q < 4; q++) acc[i][j][q] = 0.0f;

    const int f_row0 = tid >> 2, f_c0 = tid & 3;
    const int f_row1 = f_row0 + 64;
    const int f_sc0 = f_c0 ^ ((f_row0 >> 1) & 3);
    const int f_sc1 = f_c0 ^ ((f_row1 >> 1) & 3);

    const __nv_bfloat16* srcs[4] = {
        g_h0h + (size_t)m0 * KTOT, g_h0l + (size_t)m0 * KTOT,
        g_wh + (size_t)n0 * KTOT,  g_wl + (size_t)n0 * KTOT };

#pragma unroll
    for (int tI = 0; tI < 4; tI++) {
        const __nv_bfloat16* p = srcs[tI];
        *(uint4*)(smx + tI * 8192 + f_row0 * 64 + f_sc0 * 16)
            = *(const uint4*)(p + (size_t)f_row0 * KTOT + f_c0 * 8);
        *(uint4*)(smx + tI * 8192 + f_row1 * 64 + f_sc1 * 16)
            = *(const uint4*)(p + (size_t)f_row1 * KTOT + f_c0 * 8);
    }
    __syncthreads();

    for (int it = 0; it < 50; it++) {
        const int cur = it & 1;
        uint4 pf[4][2];
        if (it + 1 < 50) {
            const int koff = (it + 1) * 32;
#pragma unroll
            for (int tI = 0; tI < 4; tI++) {
                const __nv_bfloat16* p = srcs[tI] + koff;
                pf[tI][0] = *(const uint4*)(p + (size_t)f_row0 * KTOT + f_c0 * 8);
                pf[tI][1] = *(const uint4*)(p + (size_t)f_row1 * KTOT + f_c0 * 8);
            }
        }

        const uint32_t base = sbase + cur * 32768;
#pragma unroll
        for (int ks = 0; ks < 2; ks++) {
            uint32_t afh[4][4], afl[4][4], bfh[4][2], bfl[4][2];
#pragma unroll
            for (int i = 0; i < 4; i++) {
                int row = a_row_b + i * 16;
                int c = (2 * ks + a_c_b) ^ ((row >> 1) & 3);
                ldsm4(afh[i][0], afh[i][1], afh[i][2], afh[i][3],
                      base + row * 64 + c * 16);
                ldsm4(afl[i][0], afl[i][1], afl[i][2], afl[i][3],
                      base + 8192 + row * 64 + c * 16);
            }
#pragma unroll
            for (int p2 = 0; p2 < 2; p2++) {
                int row = b_row_b + p2 * 16;
                int c = (2 * ks + b_c_b) ^ ((row >> 1) & 3);
                ldsm4(bfh[p2 * 2][0], bfh[p2 * 2][1], bfh[p2 * 2 + 1][0], bfh[p2 * 2 + 1][1],
                      base + 16384 + row * 64 + c * 16);
                ldsm4(bfl[p2 * 2][0], bfl[p2 * 2][1], bfl[p2 * 2 + 1][0], bfl[p2 * 2 + 1][1],
                      base + 24576 + row * 64 + c * 16);
            }
#pragma unroll
            for (int i = 0; i < 4; i++)
#pragma unroll
                for (int j = 0; j < 4; j++) {
                    mma_bf16(acc[i][j], afh[i], bfh[j]);
                    mma_bf16(acc[i][j], afh[i], bfl[j]);
                    mma_bf16(acc[i][j], afl[i], bfh[j]);
                }
        }

        if (it + 1 < 50) {
            uint8_t* dst = smx + ((it + 1) & 1) * 32768;
#pragma unroll
            for (int tI = 0; tI < 4; tI++) {
                *(uint4*)(dst + tI * 8192 + f_row0 * 64 + f_sc0 * 16) = pf[tI][0];
                *(uint4*)(dst + tI * 8192 + f_row1 * 64 + f_sc1 * 16) = pf[tI][1];
            }
        }
        __syncthreads();
    }

    const int dd = n0 / G4;
    const size_t dbase = (size_t)dd * ((size_t)MTOT * G4);
#pragma unroll
    for (int i = 0; i < 4; i++) {
        int mrow = m0 + wm * 64 + i * 16 + (lane >> 2);
#pragma unroll
        for (int j = 0; j < 4; j++) {
            int n = n0 + wn * 32 + j * 8 + (lane & 3) * 2;
            int gc = n - dd * G4;
            float2 bv = *(const float2*)(bias + n);
            float2 o0 = { acc[i][j][0] + bv.x, acc[i][j][1] + bv.y };
            float2 o1 = { acc[i][j][2] + bv.x, acc[i][j][3] + bv.y };
            *(float2*)(g_xw + dbase + (size_t)mrow * G4 + gc) = o0;
            *(float2*)(g_xw + dbase + (size_t)(mrow + 8) * G4 + gc) = o1;
        }
    }
}

// ---------------- head ----------------
__global__ void k_head(const float* __restrict__ lin_w, const float* __restrict__ lin_b,
                       const float* __restrict__ alpha) {
    __shared__ float sl[8][UNITS];
    int warp = threadIdx.x >> 5, lane = threadIdx.x & 31;
    int m = blockIdx.x * 8 + warp;
    const __nv_bfloat16* hrh = g_h1h + (size_t)m * IN1;
    const __nv_bfloat16* hrl = g_h1l + (size_t)m * IN1;
    for (int u = 0; u < UNITS; u++) {
        float s = 0.0f;
        const float* wrow = lin_w + (size_t)u * IN1;
        for (int i = lane; i < IN1; i += 32)
            s += (__bfloat162float(hrh[i]) + __bfloat162float(hrl[i])) * wrow[i];
#pragma unroll
        for (int off = 16; off; off >>= 1) s += __shfl_xor_sync(0xffffffffu, s, off);
        if (lane == 0) sl[warp][u] = s + lin_b[u];
    }
    __syncwarp();
    float v = (lane < UNITS) ? sl[warp][lane] : -INFINITY;
    float mx = v;
#pragma unroll
    for (int off = 16; off; off >>= 1) mx = fmaxf(mx, __shfl_xor_sync(0xffffffffu, mx, off));
    float e = (lane < UNITS) ? expf(v - mx) : 0.0f;
    float se = e;
#pragma unroll
    for (int off = 16; off; off >>= 1) se += __shfl_xor_sync(0xffffffffu, se, off);
    float soft = e / se;
#pragma unroll
    for (int j = 0; j < 3; j++) {
        float a = (lane < UNITS) ? alpha[lane * 3 + j] : 0.0f;
        float ss = soft * sinf(a), cc = soft * cosf(a);
#pragma unroll
        for (int off = 16; off; off >>= 1) {
            ss += __shfl_xor_sync(0xffffffffu, ss, off);
            cc += __shfl_xor_sync(0xffffffffu, cc, off);
        }
        if (lane == 0) g_ang[(size_t)m * 3 + j] = atan2f(ss, cc);
    }
}

// ---------------- geometric chain ----------------
__global__ void k_geom(float* __restrict__ out) {
    int b = threadIdx.x;
    if (b >= BATCH) return;
    const float RL[3] = {1.329f, 1.459f, 1.525f};
    const float TA[3] = {2.034f, 2.119f, 1.937f};
    float cT[3], sT[3];
#pragma unroll
    for (int i = 0; i < 3; i++) { cT[i] = cosf(TA[i]); sT[i] = sinf(TA[i]); }
    float Ax = 0.f, Ay = 0.f, Az = 1.f;
    float Bx = 0.f, By = 1.f, Bz = 0.f;
    float Cx = 1.f, Cy = 0.f, Cz = 0.f;
    out[(0 * BATCH + b) * 3 + 0] = Ax; out[(0 * BATCH + b) * 3 + 1] = Ay; out[(0 * BATCH + b) * 3 + 2] = Az;
    out[(1 * BATCH + b) * 3 + 0] = Bx; out[(1 * BATCH + b) * 3 + 1] = By; out[(1 * BATCH + b) * 3 + 2] = Bz;
    out[(2 * BATCH + b) * 3 + 0] = Cx; out[(2 * BATCH + b) * 3 + 1] = Cy; out[(2 * BATCH + b) * 3 + 2] = Cz;
    for (int s = 0; s < T_LEN - 1; s++) {
        size_t abase = ((size_t)(s + 1) * BATCH + b) * 3;
#pragma unroll
        for (int i = 0; i < 3; i++) {
            float P = g_ang[abase + i];
            float d2x = -RL[i] * cT[i];
            float d2y = RL[i] * cosf(P) * sT[i];
            float d2z = RL[i] * sinf(P) * sT[i];
            float bcx = Cx - Bx, bcy = Cy - By, bcz = Cz - Bz;
            float rn = 1.0f / sqrtf(bcx * bcx + bcy * bcy + bcz * bcz);
            bcx *= rn; bcy *= rn; bcz *= rn;
            float abx = Bx - Ax, aby = By - Ay, abz = Bz - Az;
            float nx = aby * bcz - abz * bcy;
            float ny = abz * bcx - abx * bcz;
            float nz = abx * bcy - aby * bcx;
            float rn2 = 1.0f / sqrtf(nx * nx + ny * ny + nz * nz);
            nx *= rn2; ny *= rn2; nz *= rn2;
            float m1x = ny * bcz - nz * bcy;
            float m1y = nz * bcx - nx * bcz;
            float m1z = nx * bcy - ny * bcx;
            float Dx = bcx * d2x + m1x * d2y + nx * d2z + Cx;
            float Dy = bcy * d2x + m1y * d2y + ny * d2z + Cy;
            float Dz = bcz * d2x + m1z * d2y + nz * d2z + Cz;
            size_t obase = ((size_t)(3 + 3 * s + i) * BATCH + b) * 3;
            out[obase + 0] = Dx; out[obase + 1] = Dy; out[obase + 2] = Dz;
            Ax = Bx; Ay = By; Az = Bz;
            Bx = Cx; By = Cy; Bz = Cz;
            Cx = Dx; Cy = Dy; Cz = Dz;
        }
    }
}

// ---------------- launch ----------------
extern "C" void kernel_launch(void* const* d_in, const int* in_sizes, int n_in,
                              void* d_out, int out_size) {
    const float* seq   = (const float*)d_in[0];
    const float* w_ih0 = (const float*)d_in[2];
    const float* w_hh0 = (const float*)d_in[3];
    const float* b0    = (const float*)d_in[4];
    const float* w_ih1 = (const float*)d_in[5];
    const float* w_hh1 = (const float*)d_in[6];
    const float* b1    = (const float*)d_in[7];
    const float* lin_w = (const float*)d_in[8];
    const float* lin_b = (const float*)d_in[9];
    const float* alpha = (const float*)d_in[10];
    float* out = (float*)d_out;

    static int smem_set = 0;
    if (!smem_set) {
        cudaFuncSetAttribute(k_lstm_mma, cudaFuncAttributeMaxDynamicSharedMemorySize,
                             LSTM_SMEM);
        cudaFuncSetAttribute(k_xw1_mma, cudaFuncAttributeMaxDynamicSharedMemorySize,
                             XW1_SMEM);
        smem_set = 1;
    }

    const int n_cvt = 2 * N_WHH + N_WIH1;

    // slot #4 = k_lstm_mma(0) (the launch ncu captures)
    k_xw0<<<dim3(G4 / 128, T_LEN, 2), 128>>>(seq, w_ih0, b0);           // 1
    k_cvt_all<<<(n_cvt + 255) / 256, 256>>>(w_hh0, w_hh1, w_ih1);       // 2
    k_nop<<<1, 32>>>();                                                 // 3
    k_lstm_mma<<<dim3(HID / 16, 2), 256, LSTM_SMEM>>>(0);               // 4 <- profile
    k_xw1_mma<<<dim3(NTOT / 128, MTOT / 128), 256, XW1_SMEM>>>(b1);     // 5
    k_lstm_mma<<<dim3(HID / 16, 2), 256, LSTM_SMEM>>>(1);               // 6
    k_head<<<(T_LEN * BATCH) / 8, 256>>>(lin_w, lin_b, alpha);          // 7
    k_geom<<<1, 32>>>(out);                                             // 8
}

// round 15
// speedup vs baseline: 1.0924x; 1.0924x over previous
#include <cuda_runtime.h>
#include <cuda_bf16.h>
#include <math.h>
#include <stdint.h>

#define T_LEN 512
#define BATCH 32
#define EMB   41
#define HID   800
#define G4    3200
#define IN0   42
#define IN1   1600
#define UNITS 20
#define MTOT  (T_LEN*BATCH)   // 16384
#define NTOT  6400
#define KTOT  1600

// ---------------- device scratch ----------------
__device__ float g_xw[2u * T_LEN * BATCH * G4];
__device__ float g_ang[MTOT * 3];
__device__ __nv_bfloat16 g_h0h[(size_t)MTOT * IN1];
__device__ __nv_bfloat16 g_h0l[(size_t)MTOT * IN1];
__device__ __nv_bfloat16 g_h1h[(size_t)MTOT * IN1];
__device__ __nv_bfloat16 g_h1l[(size_t)MTOT * IN1];
__device__ __nv_bfloat16 g_wh[(size_t)NTOT * KTOT];
__device__ __nv_bfloat16 g_wl[(size_t)NTOT * KTOT];
__device__ __nv_bfloat16 g_whhh0[(size_t)2 * G4 * HID];
__device__ __nv_bfloat16 g_whhl0[(size_t)2 * G4 * HID];
__device__ __nv_bfloat16 g_whhh1[(size_t)2 * G4 * HID];
__device__ __nv_bfloat16 g_whhl1[(size_t)2 * G4 * HID];
__device__ unsigned g_barcnt[2];
__device__ unsigned g_bargen[2];

__device__ __forceinline__ float sigf(float x) { return 1.0f / (1.0f + __expf(-x)); }
__device__ __forceinline__ float tanhfast(float x) {
    float a = fabsf(x);
    float e = __expf(2.0f * a);
    float r = 1.0f - 2.0f / (e + 1.0f);
    return copysignf(r, x);
}
__device__ __forceinline__ uint32_t s2u(const void* p) {
    uint32_t a; asm("{.reg .u64 t; cvta.to.shared.u64 t, %1; cvt.u32.u64 %0, t;}" : "=r"(a) : "l"(p));
    return a;
}
__device__ __forceinline__ void ldsm4(uint32_t& r0, uint32_t& r1, uint32_t& r2,
                                      uint32_t& r3, uint32_t addr) {
    asm volatile("ldmatrix.sync.aligned.m8n8.x4.shared.b16 {%0,%1,%2,%3}, [%4];"
                 : "=r"(r0), "=r"(r1), "=r"(r2), "=r"(r3) : "r"(addr));
}
__device__ __forceinline__ void ldsm2(uint32_t& r0, uint32_t& r1, uint32_t addr) {
    asm volatile("ldmatrix.sync.aligned.m8n8.x2.shared.b16 {%0,%1}, [%2];"
                 : "=r"(r0), "=r"(r1) : "r"(addr));
}
__device__ __forceinline__ void mma_bf16(float* c, const uint32_t* a, const uint32_t* b) {
    asm volatile("mma.sync.aligned.m16n8k16.row.col.f32.bf16.bf16.f32 "
                 "{%0,%1,%2,%3}, {%4,%5,%6,%7}, {%8,%9}, {%0,%1,%2,%3};"
                 : "+f"(c[0]), "+f"(c[1]), "+f"(c[2]), "+f"(c[3])
                 : "r"(a[0]), "r"(a[1]), "r"(a[2]), "r"(a[3]), "r"(b[0]), "r"(b[1]));
}
__device__ __forceinline__ unsigned atom_add_acqrel(unsigned* p) {
    unsigned old;
    asm volatile("atom.add.acq_rel.gpu.u32 %0, [%1], 1;" : "=r"(old) : "l"(p) : "memory");
    return old;
}
__device__ __forceinline__ unsigned ld_acq(unsigned* p) {
    unsigned v;
    asm volatile("ld.acquire.gpu.u32 %0, [%1];" : "=r"(v) : "l"(p) : "memory");
    return v;
}
__device__ __forceinline__ void st_rel(unsigned* p, unsigned v) {
    asm volatile("st.release.gpu.u32 [%0], %1;" :: "l"(p), "r"(v) : "memory");
}

// ---------------- layer0 input projection ----------------
__global__ void k_xw0(const float* __restrict__ seq, const float* __restrict__ w_ih,
                      const float* __restrict__ bias) {
    __shared__ float xs[BATCH * IN0];
    int t = blockIdx.y, d = blockIdx.z;
    int g = blockIdx.x * 128 + threadIdx.x;
    for (int e = threadIdx.x; e < BATCH * IN0; e += 128) {
        int b = e / IN0, i = e % IN0;
        xs[e] = (i < EMB) ? seq[(size_t)(t * BATCH + b) * EMB + i] : (float)t;
    }
    __syncthreads();
    float acc[BATCH];
    float bv = bias[d * G4 + g];
#pragma unroll
    for (int b = 0; b < BATCH; b++) acc[b] = bv;
    const float* wrow = w_ih + (size_t)(d * G4 + g) * IN0;
#pragma unroll
    for (int i = 0; i < IN0; i++) {
        float wv = wrow[i];
#pragma unroll
        for (int b = 0; b < BATCH; b++) acc[b] += wv * xs[b * IN0 + i];
    }
    size_t base = ((size_t)(d * T_LEN + t) * BATCH) * G4 + g;
#pragma unroll
    for (int b = 0; b < BATCH; b++) g_xw[base + (size_t)b * G4] = acc[b];
}

// ---------------- combined bf16 split converter (+ barrier init) --------
#define N_WHH (2 * G4 * HID)          // 5,120,000
#define N_WIH1 (NTOT * KTOT)          // 10,240,000
__global__ void k_cvt_all(const float* __restrict__ whh0,
                          const float* __restrict__ whh1,
                          const float* __restrict__ wih1) {
    if (blockIdx.x == 0 && threadIdx.x < 2) {
        g_barcnt[threadIdx.x] = 0; g_bargen[threadIdx.x] = 0;
    }
    size_t i = (size_t)blockIdx.x * 256 + threadIdx.x;
    const float* src;
    __nv_bfloat16 *dh, *dl;
    size_t k;
    if (i < (size_t)N_WHH) {
        src = whh0; dh = g_whhh0; dl = g_whhl0; k = i;
    } else if (i < (size_t)2 * N_WHH) {
        src = whh1; dh = g_whhh1; dl = g_whhl1; k = i - N_WHH;
    } else if (i < (size_t)2 * N_WHH + N_WIH1) {
        src = wih1; dh = g_wh; dl = g_wl; k = i - 2 * (size_t)N_WHH;
    } else return;
    float v = src[k];
    __nv_bfloat16 h = __float2bfloat16(v);
    dh[k] = h;
    dl[k] = __float2bfloat16(v - __bfloat162float(h));
}

// filler so the lstm lands at ncu's captured slot (#4)
__global__ void k_nop() {}

// ---------------- persistent LSTM layer: W_hi in registers --------------
// grid (50, 2), 256 thr (8 warps = 2 K-slices x 4 N-groups, warp m32n16k400).
// Gt has its OWN smem region (no aliasing with A) -> one fewer sync per step
// and Gt stores overlap other warps' MMA tails.
#define WL_OFF 0
#define R1_OFF 103424
#define GT_OFF 206848
#define LSTM_SMEM 224256

__global__ void __launch_bounds__(256, 1)
k_lstm_mma(int layer) {
    extern __shared__ __align__(16) uint8_t sm[];
    const uint32_t sbase = s2u(sm);
    const int tid = threadIdx.x, lane = tid & 31, w = tid >> 5;
    const int wk = w >> 2;          // 0..1 : K slice (k400)
    const int ng = w & 3;           // 0..3 : N group (n16)
    const int d = blockIdx.y, j0 = blockIdx.x * 16;
    const int nblk = gridDim.x;

    __nv_bfloat16* hh = layer ? g_h1h : g_h0h;
    __nv_bfloat16* hl = layer ? g_h1l : g_h0l;
    const __nv_bfloat16* whhh = layer ? g_whhh1 : g_whhh0;
    const __nv_bfloat16* whhl = layer ? g_whhl1 : g_whhl0;
    float* Gt = (float*)(sm + GT_OFF);   // [64][68], private region

    // stage W_lo -> WL region, W_hi -> R1 region (temporarily)
    for (int idx = tid; idx < 12800; idx += 256) {
        int s = idx >= 6400;
        int e = idx - s * 6400;
        int r = e / 100, c = e % 100;
        int grow = (r >> 4) * HID + j0 + (r & 15);
        const __nv_bfloat16* src = (s ? whhh : whhl)
                                 + ((size_t)(d * G4 + grow) * HID + c * 8);
        *(uint4*)(sm + (s ? R1_OFF : WL_OFF) + r * 1616 + c * 16) = *(const uint4*)src;
    }
    __syncthreads();

    const int lr = lane & 7, q = lane >> 3;

    // preload W_hi fragments into registers: bh[sub][t16*2 + {0,1}]
    uint32_t bh[2][50];
#pragma unroll
    for (int sub = 0; sub < 2; sub++) {
        uint32_t b0 = sbase + R1_OFF
                    + (uint32_t)((ng * 16 + sub * 8 + lr) * 1616 + wk * 800 + q * 16);
#pragma unroll
        for (int g = 0; g < 12; g++)
            ldsm4(bh[sub][4 * g], bh[sub][4 * g + 1],
                  bh[sub][4 * g + 2], bh[sub][4 * g + 3], b0 + g * 64);
        uint32_t bx = sbase + R1_OFF
                    + (uint32_t)((ng * 16 + sub * 8 + lr) * 1616 + wk * 800 + 768
                                 + ((lane >> 3) & 1) * 16);
        ldsm2(bh[sub][48], bh[sub][49], bx);
    }
    __syncthreads();   // done reading W_hi; R1 region now free for A

    const int a_row_q = (q & 1) * 8 + lr;
    const int a_colq  = (q >> 1) * 16;
    uint32_t blb[2];
#pragma unroll
    for (int sub = 0; sub < 2; sub++)
        blb[sub] = sbase + WL_OFF
                 + (uint32_t)((ng * 16 + sub * 8 + lr) * 1616 + wk * 800
                              + ((lane >> 3) & 1) * 16);

    // A staging: combo = (sp, row), 4 chunk columns per thread, 25 iters
    const int combo = tid >> 2, cq = tid & 3;
    const int ssp = combo >> 5, srow = combo & 31;
    const __nv_bfloat16* hsrc_base = ssp ? hl : hh;
    const uint32_t a_dst0 = (uint32_t)(R1_OFF + ssp * 51712 + srow * 1616 + cq * 16);

    const int eb0 = tid >> 4, ejj = tid & 15;
    float creg[2] = {0.0f, 0.0f};

    for (int t = 0; t < T_LEN; t++) {
        const int tt = d ? (T_LEN - 1 - t) : t;
        const int tp = d ? tt + 1 : t - 1;

        const size_t xwb = ((size_t)(d * T_LEN + tt) * BATCH) * G4;
        float xg[2][4];
#pragma unroll
        for (int e = 0; e < 4; e++) {
            xg[0][e] = __ldg(g_xw + xwb + (size_t)eb0 * G4 + e * HID + j0 + ejj);
            xg[1][e] = __ldg(g_xw + xwb + (size_t)(eb0 + 16) * G4 + e * HID + j0 + ejj);
        }

        float acc[2][2][4];
#pragma unroll
        for (int mt = 0; mt < 2; mt++)
#pragma unroll
            for (int sub = 0; sub < 2; sub++)
#pragma unroll
                for (int i = 0; i < 4; i++) acc[mt][sub][i] = 0.0f;

        if (t > 0) {
            const __nv_bfloat16* hsrc = hsrc_base
                + (size_t)(tp * BATCH + srow) * IN1 + d * HID + cq * 8;
#pragma unroll
            for (int j = 0; j < 25; j++)
                *(uint4*)(sm + a_dst0 + j * 64) = *(const uint4*)(hsrc + j * 32);
            __syncthreads();

#pragma unroll
            for (int t16 = 0; t16 < 25; t16++) {
                uint32_t ah[2][4], al[2][4], bl0[2], bl1[2];
#pragma unroll
                for (int mt = 0; mt < 2; mt++) {
                    uint32_t aa = sbase + (uint32_t)(R1_OFF
                                + (mt * 16 + a_row_q) * 1616
                                + wk * 800 + t16 * 32 + a_colq);
                    ldsm4(ah[mt][0], ah[mt][1], ah[mt][2], ah[mt][3], aa);
                    ldsm4(al[mt][0], al[mt][1], al[mt][2], al[mt][3], aa + 51712);
                }
                ldsm2(bl0[0], bl0[1], blb[0] + t16 * 32);
                ldsm2(bl1[0], bl1[1], blb[1] + t16 * 32);
#pragma unroll
                for (int mt = 0; mt < 2; mt++) {
                    mma_bf16(acc[mt][0], ah[mt], &bh[0][t16 * 2]);
                    mma_bf16(acc[mt][0], ah[mt], bl0);
                    mma_bf16(acc[mt][0], al[mt], &bh[0][t16 * 2]);
                    mma_bf16(acc[mt][1], ah[mt], &bh[1][t16 * 2]);
                    mma_bf16(acc[mt][1], ah[mt], bl1);
                    mma_bf16(acc[mt][1], al[mt], &bh[1][t16 * 2]);
                }
            }
        }

        // Gt is private: write partials immediately (no sync needed first)
#pragma unroll
        for (int mt = 0; mt < 2; mt++)
#pragma unroll
            for (int sub = 0; sub < 2; sub++) {
                int r0 = mt * 16 + (lane >> 2);
                int c = ng * 16 + sub * 8 + (lane & 3) * 2;
                Gt[(wk * 32 + r0) * 68 + c]           = acc[mt][sub][0];
                Gt[(wk * 32 + r0) * 68 + c + 1]       = acc[mt][sub][1];
                Gt[(wk * 32 + r0 + 8) * 68 + c]       = acc[mt][sub][2];
                Gt[(wk * 32 + r0 + 8) * 68 + c + 1]   = acc[mt][sub][3];
            }
        __syncthreads();

#pragma unroll
        for (int qq = 0; qq < 2; qq++) {
            int b = eb0 + qq * 16;
            float g0 = Gt[b * 68 + ejj]        + Gt[(32 + b) * 68 + ejj]        + xg[qq][0];
            float g1 = Gt[b * 68 + 16 + ejj]   + Gt[(32 + b) * 68 + 16 + ejj]   + xg[qq][1];
            float g2 = Gt[b * 68 + 32 + ejj]   + Gt[(32 + b) * 68 + 32 + ejj]   + xg[qq][2];
            float g3 = Gt[b * 68 + 48 + ejj]   + Gt[(32 + b) * 68 + 48 + ejj]   + xg[qq][3];
            float cold = (t > 0) ? creg[qq] : 0.0f;
            float cn = sigf(g1) * cold + sigf(g0) * tanhfast(g2);
            float hn = sigf(g3) * tanhfast(cn);
            creg[qq] = cn;
            size_t ho = (size_t)(tt * BATCH + b) * IN1 + d * HID + j0 + ejj;
            __nv_bfloat16 hhi = __float2bfloat16(hn);
            hh[ho] = hhi;
            hl[ho] = __float2bfloat16(hn - __bfloat162float(hhi));
        }

        if (t + 1 < T_LEN) {
            __syncthreads();
            if (tid == 0) {
                unsigned gen = ld_acq(&g_bargen[d]);
                unsigned old = atom_add_acqrel(&g_barcnt[d]);
                if (old == (unsigned)(nblk - 1)) {
                    g_barcnt[d] = 0;
                    st_rel(&g_bargen[d], gen + 1u);
                } else {
                    while (ld_acq(&g_bargen[d]) == gen) { }
                }
            }
            __syncthreads();
        }
    }
}

// ---------------- xw1: fused single-pass bf16-split GEMM ----------------
#define XW1_SMEM 65536
__global__ void __launch_bounds__(256)
k_xw1_mma(const float* __restrict__ bias) {
    extern __shared__ __align__(1024) uint8_t smx[];
    const uint32_t sbase = s2u(smx);

    const int tid = threadIdx.x;
    const int lane = tid & 31, wid = tid >> 5;
    const int wm = wid >> 2, wn = wid & 3;
    const int lm = lane >> 3, lr = lane & 7;
    const int n0 = blockIdx.x * 128, m0 = blockIdx.y * 128;

    const int a_row_b = wm * 64 + (lm & 1) * 8 + lr;
    const int a_c_b   = (lm >> 1);
    const int b_row_b = wn * 32 + (lm >> 1) * 8 + lr;
    const int b_c_b   = (lm & 1);

    float acc[4][4][4];
#pragma unroll
    for (int i = 0; i < 4; i++)
#pragma unroll
        for (int j = 0; j < 4; j++)
#pragma unroll
            for (int q = 0; q < 4; q++) acc[i][j][q] = 0.0f;

    const int f_row0 = tid >> 2, f_c0 = tid & 3;
    const int f_row1 = f_row0 + 64;
    const int f_sc0 = f_c0 ^ ((f_row0 >> 1) & 3);
    const int f_sc1 = f_c0 ^ ((f_row1 >> 1) & 3);

    const __nv_bfloat16* srcs[4] = {
        g_h0h + (size_t)m0 * KTOT, g_h0l + (size_t)m0 * KTOT,
        g_wh + (size_t)n0 * KTOT,  g_wl + (size_t)n0 * KTOT };

#pragma unroll
    for (int tI = 0; tI < 4; tI++) {
        const __nv_bfloat16* p = srcs[tI];
        *(uint4*)(smx + tI * 8192 + f_row0 * 64 + f_sc0 * 16)
            = *(const uint4*)(p + (size_t)f_row0 * KTOT + f_c0 * 8);
        *(uint4*)(smx + tI * 8192 + f_row1 * 64 + f_sc1 * 16)
            = *(const uint4*)(p + (size_t)f_row1 * KTOT + f_c0 * 8);
    }
    __syncthreads();

    for (int it = 0; it < 50; it++) {
        const int cur = it & 1;
        uint4 pf[4][2];
        if (it + 1 < 50) {
            const int koff = (it + 1) * 32;
#pragma unroll
            for (int tI = 0; tI < 4; tI++) {
                const __nv_bfloat16* p = srcs[tI] + koff;
                pf[tI][0] = *(const uint4*)(p + (size_t)f_row0 * KTOT + f_c0 * 8);
                pf[tI][1] = *(const uint4*)(p + (size_t)f_row1 * KTOT + f_c0 * 8);
            }
        }

        const uint32_t base = sbase + cur * 32768;
#pragma unroll
        for (int ks = 0; ks < 2; ks++) {
            uint32_t afh[4][4], afl[4][4], bfh[4][2], bfl[4][2];
#pragma unroll
            for (int i = 0; i < 4; i++) {
                int row = a_row_b + i * 16;
                int c = (2 * ks + a_c_b) ^ ((row >> 1) & 3);
                ldsm4(afh[i][0], afh[i][1], afh[i][2], afh[i][3],
                      base + row * 64 + c * 16);
                ldsm4(afl[i][0], afl[i][1], afl[i][2], afl[i][3],
                      base + 8192 + row * 64 + c * 16);
            }
#pragma unroll
            for (int p2 = 0; p2 < 2; p2++) {
                int row = b_row_b + p2 * 16;
                int c = (2 * ks + b_c_b) ^ ((row >> 1) & 3);
                ldsm4(bfh[p2 * 2][0], bfh[p2 * 2][1], bfh[p2 * 2 + 1][0], bfh[p2 * 2 + 1][1],
                      base + 16384 + row * 64 + c * 16);
                ldsm4(bfl[p2 * 2][0], bfl[p2 * 2][1], bfl[p2 * 2 + 1][0], bfl[p2 * 2 + 1][1],
                      base + 24576 + row * 64 + c * 16);
            }
#pragma unroll
            for (int i = 0; i < 4; i++)
#pragma unroll
                for (int j = 0; j < 4; j++) {
                    mma_bf16(acc[i][j], afh[i], bfh[j]);
                    mma_bf16(acc[i][j], afh[i], bfl[j]);
                    mma_bf16(acc[i][j], afl[i], bfh[j]);
                }
        }

        if (it + 1 < 50) {
            uint8_t* dst = smx + ((it + 1) & 1) * 32768;
#pragma unroll
            for (int tI = 0; tI < 4; tI++) {
                *(uint4*)(dst + tI * 8192 + f_row0 * 64 + f_sc0 * 16) = pf[tI][0];
                *(uint4*)(dst + tI * 8192 + f_row1 * 64 + f_sc1 * 16) = pf[tI][1];
            }
        }
        __syncthreads();
    }

    const int dd = n0 / G4;
    const size_t dbase = (size_t)dd * ((size_t)MTOT * G4);
#pragma unroll
    for (int i = 0; i < 4; i++) {
        int mrow = m0 + wm * 64 + i * 16 + (lane >> 2);
#pragma unroll
        for (int j = 0; j < 4; j++) {
            int n = n0 + wn * 32 + j * 8 + (lane & 3) * 2;
            int gc = n - dd * G4;
            float2 bv = *(const float2*)(bias + n);
            float2 o0 = { acc[i][j][0] + bv.x, acc[i][j][1] + bv.y };
            float2 o1 = { acc[i][j][2] + bv.x, acc[i][j][3] + bv.y };
            *(float2*)(g_xw + dbase + (size_t)mrow * G4 + gc) = o0;
            *(float2*)(g_xw + dbase + (size_t)(mrow + 8) * G4 + gc) = o1;
        }
    }
}

// ---------------- head ----------------
__global__ void k_head(const float* __restrict__ lin_w, const float* __restrict__ lin_b,
                       const float* __restrict__ alpha) {
    __shared__ float sl[8][UNITS];
    int warp = threadIdx.x >> 5, lane = threadIdx.x & 31;
    int m = blockIdx.x * 8 + warp;
    const __nv_bfloat16* hrh = g_h1h + (size_t)m * IN1;
    const __nv_bfloat16* hrl = g_h1l + (size_t)m * IN1;
    for (int u = 0; u < UNITS; u++) {
        float s = 0.0f;
        const float* wrow = lin_w + (size_t)u * IN1;
        for (int i = lane; i < IN1; i += 32)
            s += (__bfloat162float(hrh[i]) + __bfloat162float(hrl[i])) * wrow[i];
#pragma unroll
        for (int off = 16; off; off >>= 1) s += __shfl_xor_sync(0xffffffffu, s, off);
        if (lane == 0) sl[warp][u] = s + lin_b[u];
    }
    __syncwarp();
    float v = (lane < UNITS) ? sl[warp][lane] : -INFINITY;
    float mx = v;
#pragma unroll
    for (int off = 16; off; off >>= 1) mx = fmaxf(mx, __shfl_xor_sync(0xffffffffu, mx, off));
    float e = (lane < UNITS) ? expf(v - mx) : 0.0f;
    float se = e;
#pragma unroll
    for (int off = 16; off; off >>= 1) se += __shfl_xor_sync(0xffffffffu, se, off);
    float soft = e / se;
#pragma unroll
    for (int j = 0; j < 3; j++) {
        float a = (lane < UNITS) ? alpha[lane * 3 + j] : 0.0f;
        float ss = soft * sinf(a), cc = soft * cosf(a);
#pragma unroll
        for (int off = 16; off; off >>= 1) {
            ss += __shfl_xor_sync(0xffffffffu, ss, off);
            cc += __shfl_xor_sync(0xffffffffu, cc, off);
        }
        if (lane == 0) g_ang[(size_t)m * 3 + j] = atan2f(ss, cc);
    }
}

// ---------------- geometric chain ----------------
__global__ void k_geom(float* __restrict__ out) {
    int b = threadIdx.x;
    if (b >= BATCH) return;
    const float RL[3] = {1.329f, 1.459f, 1.525f};
    const float TA[3] = {2.034f, 2.119f, 1.937f};
    float cT[3], sT[3];
#pragma unroll
    for (int i = 0; i < 3; i++) { cT[i] = cosf(TA[i]); sT[i] = sinf(TA[i]); }
    float Ax = 0.f, Ay = 0.f, Az = 1.f;
    float Bx = 0.f, By = 1.f, Bz = 0.f;
    float Cx = 1.f, Cy = 0.f, Cz = 0.f;
    out[(0 * BATCH + b) * 3 + 0] = Ax; out[(0 * BATCH + b) * 3 + 1] = Ay; out[(0 * BATCH + b) * 3 + 2] = Az;
    out[(1 * BATCH + b) * 3 + 0] = Bx; out[(1 * BATCH + b) * 3 + 1] = By; out[(1 * BATCH + b) * 3 + 2] = Bz;
    out[(2 * BATCH + b) * 3 + 0] = Cx; out[(2 * BATCH + b) * 3 + 1] = Cy; out[(2 * BATCH + b) * 3 + 2] = Cz;
    for (int s = 0; s < T_LEN - 1; s++) {
        size_t abase = ((size_t)(s + 1) * BATCH + b) * 3;
#pragma unroll
        for (int i = 0; i < 3; i++) {
            float P = g_ang[abase + i];
            float d2x = -RL[i] * cT[i];
            float d2y = RL[i] * cosf(P) * sT[i];
            float d2z = RL[i] * sinf(P) * sT[i];
            float bcx = Cx - Bx, bcy = Cy - By, bcz = Cz - Bz;
            float rn = 1.0f / sqrtf(bcx * bcx + bcy * bcy + bcz * bcz);
            bcx *= rn; bcy *= rn; bcz *= rn;
            float abx = Bx - Ax, aby = By - Ay, abz = Bz - Az;
            float nx = aby * bcz - abz * bcy;
            float ny = abz * bcx - abx * bcz;
            float nz = abx * bcy - aby * bcx;
            float rn2 = 1.0f / sqrtf(nx * nx + ny * ny + nz * nz);
            nx *= rn2; ny *= rn2; nz *= rn2;
            float m1x = ny * bcz - nz * bcy;
            float m1y = nz * bcx - nx * bcz;
            float m1z = nx * bcy - ny * bcx;
            float Dx = bcx * d2x + m1x * d2y + nx * d2z + Cx;
            float Dy = bcy * d2x + m1y * d2y + ny * d2z + Cy;
            float Dz = bcz * d2x + m1z * d2y + nz * d2z + Cz;
            size_t obase = ((size_t)(3 + 3 * s + i) * BATCH + b) * 3;
            out[obase + 0] = Dx; out[obase + 1] = Dy; out[obase + 2] = Dz;
            Ax = Bx; Ay = By; Az = Bz;
            Bx = Cx; By = Cy; Bz = Cz;
            Cx = Dx; Cy = Dy; Cz = Dz;
        }
    }
}

// ---------------- launch ----------------
extern "C" void kernel_launch(void* const* d_in, const int* in_sizes, int n_in,
                              void* d_out, int out_size) {
    const float* seq   = (const float*)d_in[0];
    const float* w_ih0 = (const float*)d_in[2];
    const float* w_hh0 = (const float*)d_in[3];
    const float* b0    = (const float*)d_in[4];
    const float* w_ih1 = (const float*)d_in[5];
    const float* w_hh1 = (const float*)d_in[6];
    const float* b1    = (const float*)d_in[7];
    const float* lin_w = (const float*)d_in[8];
    const float* lin_b = (const float*)d_in[9];
    const float* alpha = (const float*)d_in[10];
    float* out = (float*)d_out;

    static int smem_set = 0;
    if (!smem_set) {
        cudaFuncSetAttribute(k_lstm_mma, cudaFuncAttributeMaxDynamicSharedMemorySize,
                             LSTM_SMEM);
        cudaFuncSetAttribute(k_xw1_mma, cudaFuncAttributeMaxDynamicSharedMemorySize,
                             XW1_SMEM);
        smem_set = 1;
    }

    const int n_cvt = 2 * N_WHH + N_WIH1;

    // slot #4 = k_lstm_mma(0) (the launch ncu captures)
    k_xw0<<<dim3(G4 / 128, T_LEN, 2), 128>>>(seq, w_ih0, b0);           // 1
    k_cvt_all<<<(n_cvt + 255) / 256, 256>>>(w_hh0, w_hh1, w_ih1);       // 2
    k_nop<<<1, 32>>>();                                                 // 3
    k_lstm_mma<<<dim3(HID / 16, 2), 256, LSTM_SMEM>>>(0);               // 4 <- profile
    k_xw1_mma<<<dim3(NTOT / 128, MTOT / 128), 256, XW1_SMEM>>>(b1);     // 5
    k_lstm_mma<<<dim3(HID / 16, 2), 256, LSTM_SMEM>>>(1);               // 6
    k_head<<<(T_LEN * BATCH) / 8, 256>>>(lin_w, lin_b, alpha);          // 7
    k_geom<<<1, 32>>>(out);                                             // 8
}